// round 4
// baseline (speedup 1.0000x reference)
#include <cuda_runtime.h>
#include <cuda_bf16.h>
#include <mma.h>
#include <math.h>
#include <stdint.h>

using namespace nvcuda;

// ---------------------------------------------------------------------------
// Problem constants
// ---------------------------------------------------------------------------
#define B_ 2
#define T_ 2048
#define D_ 2048
#define H_ 16
#define DH_ 128
#define DR_ 64
#define DL_ 512
#define WINDOW_HALF 256
#define STRIDE_ 64
#define GLOBAL_ 128
static __device__ __constant__ float SCALE_C      = 0.08838834764831845f;   // 1/sqrt(128)
static __device__ __constant__ float SCALE_ROPE_C = 0.125f;                 // 1/sqrt(64)
#define YARN_F 1.3465735902799727f  // 0.1*ln(32)+1

#define MT (B_*T_)            // 4096 rows

// ---------------------------------------------------------------------------
// Scratch (device globals; no allocation allowed)
// ---------------------------------------------------------------------------
__device__ float g_qc [(size_t)MT * D_];          // [4096,2048]
__device__ float g_ckv[(size_t)MT * DL_];         // [4096,512]
__device__ float g_kc [(size_t)MT * D_];
__device__ float g_vc [(size_t)MT * D_];
__device__ float g_qr [(size_t)MT * (H_*DR_)];    // [4096,1024]
__device__ float g_kr [(size_t)MT * (H_*DR_)];
__device__ float g_ao [(size_t)MT * D_];

// ---------------------------------------------------------------------------
// 3xTF32 tensor-core GEMM: C[M,N] = A[M,K] @ B[K,N], row-major.
// M%128==0, N%128==0, K%16==0.
// Split each operand x = hi + lo (tf32-rounded, subtraction exact in fp32);
// compute Ah*Bh + Al*Bh + Ah*Bl (fp32 accumulate) -> ~fp32 accuracy.
// Block tile 128x128x16, 8 warps, warp tile 64x32 (4x2 wmma 16x16x8 tiles).
// DOUBLE-BUFFERED dynamic smem: one __syncthreads per K-tile; LDG prefetch
// issued before the mma block, split/STS into the alternate buffer after.
// ---------------------------------------------------------------------------
#define BM 128
#define BN 128
#define BKT 16
#define ALD 20    // A smem leading dim (16 + 4 pad), mult of 4 for wmma
#define BLD 132   // B smem leading dim (128 + 4 pad), mult of 4 for wmma

#define A_FL (BM * ALD)              // 2560 floats
#define B_FL (BKT * BLD)             // 2112 floats
#define STG_FL (2 * A_FL + 2 * B_FL) // 9344 floats per stage
#define GEMM_SMEM_BYTES (2 * STG_FL * 4)   // 74752 bytes

__device__ __forceinline__ void split_tf32(float v, float* __restrict__ hi,
                                           float* __restrict__ lo) {
    float h = wmma::__float_to_tf32(v);
    *hi = h;
    *lo = wmma::__float_to_tf32(v - h);
}

__global__ __launch_bounds__(256, 2)
void sgemm_tf32(const float* __restrict__ A, const float* __restrict__ B,
                float* __restrict__ C, int M, int N, int K) {
    extern __shared__ float smem[];

    const int tid  = threadIdx.x;
    const int warp = tid >> 5;
    const int wr = warp >> 2;    // 0..1  (warp row  -> 64 rows)
    const int wc = warp & 3;     // 0..3  (warp col  -> 32 cols)

    const float* Abase = A + (size_t)(blockIdx.y * BM) * K;
    const float* Bbase = B + (size_t)(blockIdx.x * BN);
    float*       Cbase = C + (size_t)(blockIdx.y * BM) * N + blockIdx.x * BN;

    // staging: A tile 128x16 = 512 float4, B tile 16x128 = 512 float4;
    // each thread handles float4 idx = tid*2 + {0,1} of each.
    const int idx0 = tid * 2;
    const int aR0 = idx0 >> 2,        aC0 = (idx0 & 3) * 4;
    const int aR1 = (idx0 + 1) >> 2,  aC1 = ((idx0 + 1) & 3) * 4;
    const int bR0 = idx0 >> 5,        bC0 = (idx0 & 31) * 4;
    const int bR1 = (idx0 + 1) >> 5,  bC1 = ((idx0 + 1) & 31) * 4;

    wmma::fragment<wmma::accumulator, 16, 16, 8, float> acc[4][2];
#pragma unroll
    for (int i = 0; i < 4; i++)
#pragma unroll
        for (int j = 0; j < 2; j++) wmma::fill_fragment(acc[i][j], 0.0f);

    const int nIter = K / BKT;

    // split+store one staged tile (registers -> smem stage s)
    auto stage_store = [&](int s, const float4& a0, const float4& a1,
                           const float4& b0, const float4& b1) {
        float* Ah = smem + s * STG_FL;
        float* Al = Ah + A_FL;
        float* Bh = Al + A_FL;
        float* Bl = Bh + B_FL;
        split_tf32(a0.x, &Ah[aR0*ALD + aC0+0], &Al[aR0*ALD + aC0+0]);
        split_tf32(a0.y, &Ah[aR0*ALD + aC0+1], &Al[aR0*ALD + aC0+1]);
        split_tf32(a0.z, &Ah[aR0*ALD + aC0+2], &Al[aR0*ALD + aC0+2]);
        split_tf32(a0.w, &Ah[aR0*ALD + aC0+3], &Al[aR0*ALD + aC0+3]);
        split_tf32(a1.x, &Ah[aR1*ALD + aC1+0], &Al[aR1*ALD + aC1+0]);
        split_tf32(a1.y, &Ah[aR1*ALD + aC1+1], &Al[aR1*ALD + aC1+1]);
        split_tf32(a1.z, &Ah[aR1*ALD + aC1+2], &Al[aR1*ALD + aC1+2]);
        split_tf32(a1.w, &Ah[aR1*ALD + aC1+3], &Al[aR1*ALD + aC1+3]);
        split_tf32(b0.x, &Bh[bR0*BLD + bC0+0], &Bl[bR0*BLD + bC0+0]);
        split_tf32(b0.y, &Bh[bR0*BLD + bC0+1], &Bl[bR0*BLD + bC0+1]);
        split_tf32(b0.z, &Bh[bR0*BLD + bC0+2], &Bl[bR0*BLD + bC0+2]);
        split_tf32(b0.w, &Bh[bR0*BLD + bC0+3], &Bl[bR0*BLD + bC0+3]);
        split_tf32(b1.x, &Bh[bR1*BLD + bC1+0], &Bl[bR1*BLD + bC1+0]);
        split_tf32(b1.y, &Bh[bR1*BLD + bC1+1], &Bl[bR1*BLD + bC1+1]);
        split_tf32(b1.z, &Bh[bR1*BLD + bC1+2], &Bl[bR1*BLD + bC1+2]);
        split_tf32(b1.w, &Bh[bR1*BLD + bC1+3], &Bl[bR1*BLD + bC1+3]);
    };

    // prologue: fetch + stage tile 0 into buffer 0
    {
        float4 a0 = *(const float4*)(Abase + (size_t)aR0 * K + aC0);
        float4 a1 = *(const float4*)(Abase + (size_t)aR1 * K + aC1);
        float4 b0 = *(const float4*)(Bbase + (size_t)bR0 * N + bC0);
        float4 b1 = *(const float4*)(Bbase + (size_t)bR1 * N + bC1);
        stage_store(0, a0, a1, b0, b1);
    }
    __syncthreads();

    int cur = 0;
    for (int kt = 0; kt < nIter; kt++) {
        // prefetch next tile into registers (LDG issued before the mma block)
        float4 a0, a1, b0, b1;
        const bool has = (kt + 1) < nIter;
        if (has) {
            int k0 = (kt + 1) * BKT;
            a0 = *(const float4*)(Abase + (size_t)aR0 * K + k0 + aC0);
            a1 = *(const float4*)(Abase + (size_t)aR1 * K + k0 + aC1);
            b0 = *(const float4*)(Bbase + (size_t)(k0 + bR0) * N + bC0);
            b1 = *(const float4*)(Bbase + (size_t)(k0 + bR1) * N + bC1);
        }

        const float* Ah = smem + cur * STG_FL;
        const float* Al = Ah + A_FL;
        const float* Bh = Al + A_FL;
        const float* Bl = Bh + B_FL;

#pragma unroll
        for (int ks = 0; ks < 2; ks++) {
            wmma::fragment<wmma::matrix_a, 16, 16, 8, wmma::precision::tf32, wmma::row_major> fah[4], fal[4];
#pragma unroll
            for (int i = 0; i < 4; i++) {
                wmma::load_matrix_sync(fah[i], &Ah[(wr * 64 + i * 16) * ALD + ks * 8], ALD);
                wmma::load_matrix_sync(fal[i], &Al[(wr * 64 + i * 16) * ALD + ks * 8], ALD);
            }
#pragma unroll
            for (int j = 0; j < 2; j++) {
                wmma::fragment<wmma::matrix_b, 16, 16, 8, wmma::precision::tf32, wmma::row_major> fbh, fbl;
                wmma::load_matrix_sync(fbh, &Bh[(ks * 8) * BLD + wc * 32 + j * 16], BLD);
                wmma::load_matrix_sync(fbl, &Bl[(ks * 8) * BLD + wc * 32 + j * 16], BLD);
#pragma unroll
                for (int i = 0; i < 4; i++) {
                    wmma::mma_sync(acc[i][j], fah[i], fbh, acc[i][j]);
                    wmma::mma_sync(acc[i][j], fal[i], fbh, acc[i][j]);
                    wmma::mma_sync(acc[i][j], fah[i], fbl, acc[i][j]);
                }
            }
        }

        if (has) stage_store(cur ^ 1, a0, a1, b0, b1);
        __syncthreads();
        cur ^= 1;
    }

#pragma unroll
    for (int i = 0; i < 4; i++)
#pragma unroll
        for (int j = 0; j < 2; j++)
            wmma::store_matrix_sync(Cbase + (size_t)(wr * 64 + i * 16) * N + wc * 32 + j * 16,
                                    acc[i][j], N, wmma::mem_row_major);
}

// ---------------------------------------------------------------------------
// YaRN RoPE, in place on [B*T, H*DR] buffer. One thread per rotation pair.
// ---------------------------------------------------------------------------
__global__ void rope_kernel(float* __restrict__ buf) {
    int idx = blockIdx.x * blockDim.x + threadIdx.x;   // over B*T*H*(DR/2)
    int i  = idx & 31;
    int h  = (idx >> 5) & (H_ - 1);
    int bt = idx >> 9;
    if (bt >= MT) return;
    int t = bt & (T_ - 1);

    float fi = (float)i;
    float base_inv = powf(10000.0f, -(2.0f * fi) / 64.0f);
    float ramp = fminf(fmaxf((fi - 1.0f) / 31.0f, 0.0f), 1.0f);
    float inv = base_inv * (1.0f - ramp) + (base_inv * (1.0f / 32.0f)) * ramp;
    float fr = (float)t * inv;
    float c = cosf(fr) * YARN_F;
    float s = sinf(fr) * YARN_F;

    size_t base = (size_t)bt * (H_ * DR_) + h * DR_;
    float x1 = buf[base + i];
    float x2 = buf[base + i + 32];
    buf[base + i]      = x1 * c - x2 * s;
    buf[base + i + 32] = x2 * c + x1 * s;
}

// ---------------------------------------------------------------------------
// Sparse attention.
// Block = (q_tile of 32, head, batch); 256 threads = 8 warps, warp owns 4
// queries, lane owns 1 key per 32-key batch. Candidate keys enumerated
// disjointly: dense global [0,min(lo,128)), dilated {64j in [128,lo)},
// window [lo, q0+31]. Full mask re-applied per (q,k) pair.
// ---------------------------------------------------------------------------
#define KT 32
#define QT 32
#define KSTR 193   // 192 + 1 pad -> conflict-free per-lane row reads

__global__ __launch_bounds__(256, 2)
void attn_kernel(const float* __restrict__ qc, const float* __restrict__ kc,
                 const float* __restrict__ vc, const float* __restrict__ qr,
                 const float* __restrict__ kr, float* __restrict__ ao) {
    __shared__ int   keys_sm[512];
    __shared__ float Ks[KT * KSTR];     // [kc*SCALE | kr*SCALE_ROPE] per key
    __shared__ float Vs[KT * 128];

    const int tid  = threadIdx.x;
    const int lane = tid & 31;
    const int warp = tid >> 5;
    const int q0 = blockIdx.x * QT;
    const int h  = blockIdx.y;
    const int b  = blockIdx.z;

    const float scale_c = SCALE_C, scale_r = SCALE_ROPE_C;

    // --- enumerate candidate keys ---
    int lo   = max(0, q0 - WINDOW_HALF);
    int aEnd = min(lo, GLOBAL_);
    int nB   = (lo > GLOBAL_) ? (((lo - 1) >> 6) - 1) : 0;
    int hi   = q0 + QT - 1;
    int nW   = hi - lo + 1;
    int cnt  = aEnd + nB + nW;
    int cntPad = (cnt + KT - 1) & ~(KT - 1);
    for (int s = tid; s < cntPad; s += 256) {
        int k;
        if (s < aEnd)           k = s;
        else if (s < aEnd + nB) k = GLOBAL_ + 64 * (s - aEnd);
        else if (s < cnt)       k = lo + (s - aEnd - nB);
        else                    k = -1;
        keys_sm[s] = k;
    }

    // --- load queries into registers: qreg[i][j] = q_i[j*32+lane] ---
    const float* qc_base = qc + ((size_t)b * T_) * D_ + h * DH_;
    const float* qr_base = qr + ((size_t)b * T_) * (H_ * DR_) + h * DR_;
    float qreg[4][6];
#pragma unroll
    for (int i = 0; i < 4; i++) {
        int q = q0 + warp * 4 + i;
#pragma unroll
        for (int j = 0; j < 4; j++)
            qreg[i][j] = qc_base[(size_t)q * D_ + j * 32 + lane];
#pragma unroll
        for (int j = 0; j < 2; j++)
            qreg[i][4 + j] = qr_base[(size_t)q * (H_ * DR_) + j * 32 + lane];
    }

    const float* kc_base = kc + ((size_t)b * T_) * D_ + h * DH_;
    const float* kr_base = kr + ((size_t)b * T_) * (H_ * DR_) + h * DR_;
    const float* vc_base = vc + ((size_t)b * T_) * D_ + h * DH_;

    float m[4], l[4], acc[4][4];
#pragma unroll
    for (int i = 0; i < 4; i++) {
        m[i] = -INFINITY; l[i] = 0.f;
#pragma unroll
        for (int j = 0; j < 4; j++) acc[i][j] = 0.f;
    }

    __syncthreads();

    for (int s0 = 0; s0 < cntPad; s0 += KT) {
        // ---- stage K (scaled) and V tiles ----
        for (int idx = tid; idx < KT * 192; idx += 256) {
            int r = idx / 192, d = idx - r * 192;
            int kid = keys_sm[s0 + r];
            int krow = kid < 0 ? 0 : kid;
            float v;
            if (d < 128) v = kc_base[(size_t)krow * D_ + d] * scale_c;
            else         v = kr_base[(size_t)krow * (H_ * DR_) + (d - 128)] * scale_r;
            Ks[r * KSTR + d] = v;
        }
        for (int idx = tid; idx < KT * 128; idx += 256) {
            int r = idx >> 7, d = idx & 127;
            int kid = keys_sm[s0 + r];
            int krow = kid < 0 ? 0 : kid;
            Vs[r * 128 + d] = vc_base[(size_t)krow * D_ + d];
        }
        __syncthreads();

        // ---- scores: lane's key vs warp's 4 queries ----
        int myk = keys_sm[s0 + lane];
        float sc[4] = {0.f, 0.f, 0.f, 0.f};
        const float* krow_sm = &Ks[lane * KSTR];
#pragma unroll
        for (int j = 0; j < 6; j++) {
#pragma unroll 8
            for (int u = 0; u < 32; u++) {
                float kd = krow_sm[j * 32 + u];
                sc[0] += __shfl_sync(0xffffffffu, qreg[0][j], u) * kd;
                sc[1] += __shfl_sync(0xffffffffu, qreg[1][j], u) * kd;
                sc[2] += __shfl_sync(0xffffffffu, qreg[2][j], u) * kd;
                sc[3] += __shfl_sync(0xffffffffu, qreg[3][j], u) * kd;
            }
        }

        // ---- mask + online softmax per query ----
        float pv[4];
#pragma unroll
        for (int i = 0; i < 4; i++) {
            int q = q0 + warp * 4 + i;
            bool valid = (myk >= 0) & (myk <= q) &&
                         ((q - myk) <= WINDOW_HALF || myk < GLOBAL_ ||
                          (myk & (STRIDE_ - 1)) == 0);
            float si = valid ? sc[i] : -INFINITY;
            float mx = si;
#pragma unroll
            for (int off = 16; off; off >>= 1)
                mx = fmaxf(mx, __shfl_xor_sync(0xffffffffu, mx, off));
            float mnew = fmaxf(m[i], mx);
            float corr = __expf(m[i] - mnew);          // exp(-inf)=0 on first tile
            float p = __expf(si - mnew);
            float ps = p;
#pragma unroll
            for (int off = 16; off; off >>= 1)
                ps += __shfl_xor_sync(0xffffffffu, ps, off);
            l[i] = l[i] * corr + ps;
            m[i] = mnew;
#pragma unroll
            for (int j = 0; j < 4; j++) acc[i][j] *= corr;
            pv[i] = p;
        }

        // ---- accumulate V ----
#pragma unroll 8
        for (int u = 0; u < 32; u++) {
            float v0 = Vs[u * 128 + lane];
            float v1 = Vs[u * 128 + 32 + lane];
            float v2 = Vs[u * 128 + 64 + lane];
            float v3 = Vs[u * 128 + 96 + lane];
#pragma unroll
            for (int i = 0; i < 4; i++) {
                float pk = __shfl_sync(0xffffffffu, pv[i], u);
                acc[i][0] += pk * v0;
                acc[i][1] += pk * v1;
                acc[i][2] += pk * v2;
                acc[i][3] += pk * v3;
            }
        }
        __syncthreads();
    }

    // ---- epilogue ----
    float* ao_base = ao + ((size_t)b * T_) * D_ + h * DH_;
#pragma unroll
    for (int i = 0; i < 4; i++) {
        int q = q0 + warp * 4 + i;
        float inv_l = 1.0f / l[i];
#pragma unroll
        for (int j = 0; j < 4; j++)
            ao_base[(size_t)q * D_ + j * 32 + lane] = acc[i][j] * inv_l;
    }
}

// ---------------------------------------------------------------------------
// Launch
// ---------------------------------------------------------------------------
extern "C" void kernel_launch(void* const* d_in, const int* in_sizes, int n_in,
                              void* d_out, int out_size) {
    (void)in_sizes; (void)n_in; (void)out_size;
    const float* x     = (const float*)d_in[0];
    const float* w_q   = (const float*)d_in[1];
    const float* w_dkv = (const float*)d_in[2];
    const float* w_uk  = (const float*)d_in[3];
    const float* w_uv  = (const float*)d_in[4];
    const float* w_qp  = (const float*)d_in[5];
    const float* w_kp  = (const float*)d_in[6];
    const float* w_o   = (const float*)d_in[7];
    float* out = (float*)d_out;

    float *qc, *ckv, *kc, *vc, *qr, *kr, *ao;
    cudaGetSymbolAddress((void**)&qc,  g_qc);
    cudaGetSymbolAddress((void**)&ckv, g_ckv);
    cudaGetSymbolAddress((void**)&kc,  g_kc);
    cudaGetSymbolAddress((void**)&vc,  g_vc);
    cudaGetSymbolAddress((void**)&qr,  g_qr);
    cudaGetSymbolAddress((void**)&kr,  g_kr);
    cudaGetSymbolAddress((void**)&ao,  g_ao);

    // opt-in to >48KB dynamic smem for the GEMM (host-side, idempotent,
    // not a stream op -> graph-capture safe, no allocation)
    cudaFuncSetAttribute(sgemm_tf32, cudaFuncAttributeMaxDynamicSharedMemorySize,
                         GEMM_SMEM_BYTES);

    // projections (tensor-core 3xTF32, double-buffered)
    sgemm_tf32<<<dim3(D_ / BN, MT / BM), 256, GEMM_SMEM_BYTES>>>(x,   w_q,   qc,  MT, D_,  D_);
    sgemm_tf32<<<dim3(DL_ / BN, MT / BM), 256, GEMM_SMEM_BYTES>>>(x,  w_dkv, ckv, MT, DL_, D_);
    sgemm_tf32<<<dim3(D_ / BN, MT / BM), 256, GEMM_SMEM_BYTES>>>(ckv, w_uk,  kc,  MT, D_,  DL_);
    sgemm_tf32<<<dim3(D_ / BN, MT / BM), 256, GEMM_SMEM_BYTES>>>(ckv, w_uv,  vc,  MT, D_,  DL_);
    sgemm_tf32<<<dim3((H_ * DR_) / BN, MT / BM), 256, GEMM_SMEM_BYTES>>>(x, w_qp, qr, MT, H_ * DR_, D_);
    sgemm_tf32<<<dim3((H_ * DR_) / BN, MT / BM), 256, GEMM_SMEM_BYTES>>>(x, w_kp, kr, MT, H_ * DR_, D_);

    // rope (in place)
    int ropeThreads = MT * H_ * (DR_ / 2);
    rope_kernel<<<ropeThreads / 256, 256>>>(qr);
    rope_kernel<<<ropeThreads / 256, 256>>>(kr);

    // sparse attention
    attn_kernel<<<dim3(T_ / QT, H_, B_), 256>>>(qc, kc, vc, qr, kr, ao);

    // output projection
    sgemm_tf32<<<dim3(D_ / BN, MT / BM), 256, GEMM_SMEM_BYTES>>>(ao, w_o, out, MT, D_, D_);
}

// round 6
// speedup vs baseline: 1.1564x; 1.1564x over previous
#include <cuda_runtime.h>
#include <cuda_bf16.h>
#include <mma.h>
#include <math.h>
#include <stdint.h>

using namespace nvcuda;

// ---------------------------------------------------------------------------
// Problem constants
// ---------------------------------------------------------------------------
#define B_ 2
#define T_ 2048
#define D_ 2048
#define H_ 16
#define DH_ 128
#define DR_ 64
#define DL_ 512
#define WINDOW_HALF 256
#define STRIDE_ 64
#define GLOBAL_ 128
#define SCALE_CF      0.08838834764831845f   // 1/sqrt(128)
#define SCALE_ROPE_CF 0.125f                 // 1/sqrt(64)
#define YARN_F 1.3465735902799727f  // 0.1*ln(32)+1
#define LOG2_10000 13.287712379549449f

#define MT (B_*T_)            // 4096 rows

// ---------------------------------------------------------------------------
// Scratch (device globals; no allocation allowed)
// ---------------------------------------------------------------------------
__device__ float g_qc [(size_t)MT * D_];          // [4096,2048]
__device__ float g_ckv[(size_t)MT * DL_];         // [4096,512]
__device__ float g_kc [(size_t)MT * D_];
__device__ float g_vc [(size_t)MT * D_];
__device__ float g_qr [(size_t)MT * (H_*DR_)];    // [4096,1024]
__device__ float g_kr [(size_t)MT * (H_*DR_)];
__device__ float g_ao [(size_t)MT * D_];

// ---------------------------------------------------------------------------
// 3xTF32 tensor-core GEMM (measured R4: 340us/large launch, tensor=49.9%).
// ---------------------------------------------------------------------------
#define BM 128
#define BN 128
#define BKT 16
#define ALD 20
#define BLD 132

#define A_FL (BM * ALD)
#define B_FL (BKT * BLD)
#define STG_FL (2 * A_FL + 2 * B_FL)
#define GEMM_SMEM_BYTES (2 * STG_FL * 4)

__device__ __forceinline__ void split_tf32(float v, float* __restrict__ hi,
                                           float* __restrict__ lo) {
    float h = wmma::__float_to_tf32(v);
    *hi = h;
    *lo = wmma::__float_to_tf32(v - h);
}

__global__ __launch_bounds__(256, 2)
void sgemm_tf32(const float* __restrict__ A, const float* __restrict__ B,
                float* __restrict__ C, int M, int N, int K) {
    extern __shared__ float smem[];

    const int tid  = threadIdx.x;
    const int warp = tid >> 5;
    const int wr = warp >> 2;
    const int wc = warp & 3;

    const float* Abase = A + (size_t)(blockIdx.y * BM) * K;
    const float* Bbase = B + (size_t)(blockIdx.x * BN);
    float*       Cbase = C + (size_t)(blockIdx.y * BM) * N + blockIdx.x * BN;

    const int idx0 = tid * 2;
    const int aR0 = idx0 >> 2,        aC0 = (idx0 & 3) * 4;
    const int aR1 = (idx0 + 1) >> 2,  aC1 = ((idx0 + 1) & 3) * 4;
    const int bR0 = idx0 >> 5,        bC0 = (idx0 & 31) * 4;
    const int bR1 = (idx0 + 1) >> 5,  bC1 = ((idx0 + 1) & 31) * 4;

    wmma::fragment<wmma::accumulator, 16, 16, 8, float> acc[4][2];
#pragma unroll
    for (int i = 0; i < 4; i++)
#pragma unroll
        for (int j = 0; j < 2; j++) wmma::fill_fragment(acc[i][j], 0.0f);

    const int nIter = K / BKT;

    auto stage_store = [&](int s, const float4& a0, const float4& a1,
                           const float4& b0, const float4& b1) {
        float* Ah = smem + s * STG_FL;
        float* Al = Ah + A_FL;
        float* Bh = Al + A_FL;
        float* Bl = Bh + B_FL;
        split_tf32(a0.x, &Ah[aR0*ALD + aC0+0], &Al[aR0*ALD + aC0+0]);
        split_tf32(a0.y, &Ah[aR0*ALD + aC0+1], &Al[aR0*ALD + aC0+1]);
        split_tf32(a0.z, &Ah[aR0*ALD + aC0+2], &Al[aR0*ALD + aC0+2]);
        split_tf32(a0.w, &Ah[aR0*ALD + aC0+3], &Al[aR0*ALD + aC0+3]);
        split_tf32(a1.x, &Ah[aR1*ALD + aC1+0], &Al[aR1*ALD + aC1+0]);
        split_tf32(a1.y, &Ah[aR1*ALD + aC1+1], &Al[aR1*ALD + aC1+1]);
        split_tf32(a1.z, &Ah[aR1*ALD + aC1+2], &Al[aR1*ALD + aC1+2]);
        split_tf32(a1.w, &Ah[aR1*ALD + aC1+3], &Al[aR1*ALD + aC1+3]);
        split_tf32(b0.x, &Bh[bR0*BLD + bC0+0], &Bl[bR0*BLD + bC0+0]);
        split_tf32(b0.y, &Bh[bR0*BLD + bC0+1], &Bl[bR0*BLD + bC0+1]);
        split_tf32(b0.z, &Bh[bR0*BLD + bC0+2], &Bl[bR0*BLD + bC0+2]);
        split_tf32(b0.w, &Bh[bR0*BLD + bC0+3], &Bl[bR0*BLD + bC0+3]);
        split_tf32(b1.x, &Bh[bR1*BLD + bC1+0], &Bl[bR1*BLD + bC1+0]);
        split_tf32(b1.y, &Bh[bR1*BLD + bC1+1], &Bl[bR1*BLD + bC1+1]);
        split_tf32(b1.z, &Bh[bR1*BLD + bC1+2], &Bl[bR1*BLD + bC1+2]);
        split_tf32(b1.w, &Bh[bR1*BLD + bC1+3], &Bl[bR1*BLD + bC1+3]);
    };

    {
        float4 a0 = *(const float4*)(Abase + (size_t)aR0 * K + aC0);
        float4 a1 = *(const float4*)(Abase + (size_t)aR1 * K + aC1);
        float4 b0 = *(const float4*)(Bbase + (size_t)bR0 * N + bC0);
        float4 b1 = *(const float4*)(Bbase + (size_t)bR1 * N + bC1);
        stage_store(0, a0, a1, b0, b1);
    }
    __syncthreads();

    int cur = 0;
    for (int kt = 0; kt < nIter; kt++) {
        float4 a0, a1, b0, b1;
        const bool has = (kt + 1) < nIter;
        if (has) {
            int k0 = (kt + 1) * BKT;
            a0 = *(const float4*)(Abase + (size_t)aR0 * K + k0 + aC0);
            a1 = *(const float4*)(Abase + (size_t)aR1 * K + k0 + aC1);
            b0 = *(const float4*)(Bbase + (size_t)(k0 + bR0) * N + bC0);
            b1 = *(const float4*)(Bbase + (size_t)(k0 + bR1) * N + bC1);
        }

        const float* Ah = smem + cur * STG_FL;
        const float* Al = Ah + A_FL;
        const float* Bh = Al + A_FL;
        const float* Bl = Bh + B_FL;

#pragma unroll
        for (int ks = 0; ks < 2; ks++) {
            wmma::fragment<wmma::matrix_a, 16, 16, 8, wmma::precision::tf32, wmma::row_major> fah[4], fal[4];
#pragma unroll
            for (int i = 0; i < 4; i++) {
                wmma::load_matrix_sync(fah[i], &Ah[(wr * 64 + i * 16) * ALD + ks * 8], ALD);
                wmma::load_matrix_sync(fal[i], &Al[(wr * 64 + i * 16) * ALD + ks * 8], ALD);
            }
#pragma unroll
            for (int j = 0; j < 2; j++) {
                wmma::fragment<wmma::matrix_b, 16, 16, 8, wmma::precision::tf32, wmma::row_major> fbh, fbl;
                wmma::load_matrix_sync(fbh, &Bh[(ks * 8) * BLD + wc * 32 + j * 16], BLD);
                wmma::load_matrix_sync(fbl, &Bl[(ks * 8) * BLD + wc * 32 + j * 16], BLD);
#pragma unroll
                for (int i = 0; i < 4; i++) {
                    wmma::mma_sync(acc[i][j], fah[i], fbh, acc[i][j]);
                    wmma::mma_sync(acc[i][j], fal[i], fbh, acc[i][j]);
                    wmma::mma_sync(acc[i][j], fah[i], fbl, acc[i][j]);
                }
            }
        }

        if (has) stage_store(cur ^ 1, a0, a1, b0, b1);
        __syncthreads();
        cur ^= 1;
    }

#pragma unroll
    for (int i = 0; i < 4; i++)
#pragma unroll
        for (int j = 0; j < 2; j++)
            wmma::store_matrix_sync(Cbase + (size_t)(wr * 64 + i * 16) * N + wc * 32 + j * 16,
                                    acc[i][j], N, wmma::mem_row_major);
}

// ---------------------------------------------------------------------------
// YaRN RoPE, in place on [B*T, H*DR] buffer. One thread per rotation pair.
// ---------------------------------------------------------------------------
__global__ void rope_kernel(float* __restrict__ buf) {
    int idx = blockIdx.x * blockDim.x + threadIdx.x;
    int i  = idx & 31;
    int h  = (idx >> 5) & (H_ - 1);
    int bt = idx >> 9;
    if (bt >= MT) return;
    int t = bt & (T_ - 1);

    float fi = (float)i;
    float base_inv = exp2f(-(2.0f * fi / 64.0f) * LOG2_10000);
    float ramp = fminf(fmaxf((fi - 1.0f) / 31.0f, 0.0f), 1.0f);
    float inv = base_inv * (1.0f - ramp) + (base_inv * (1.0f / 32.0f)) * ramp;
    float fr = (float)t * inv;
    float c = cosf(fr) * YARN_F;
    float s = sinf(fr) * YARN_F;

    size_t base = (size_t)bt * (H_ * DR_) + h * DR_;
    float x1 = buf[base + i];
    float x2 = buf[base + i + 32];
    buf[base + i]      = x1 * c - x2 * s;
    buf[base + i + 32] = x2 * c + x1 * s;
}

// ---------------------------------------------------------------------------
// Sparse attention, shuffle-free float4 layout.
// Block = (q_tile of 32, head, batch); 256 threads = 8 warps; warp owns 4
// queries; lane owns 1 key per 32-key tile (scores) / 4 dims (V accum).
// Q is pre-scaled and staged to smem once; K/V staged per tile; P passed
// through smem (broadcast reads) instead of shuffles.
// Dynamic smem (floats): Qs[32][192] | Ks[32][196] | Vs[32][128] |
// Ps[8][4][32] | keys[512]  = 18048 floats = 72192 B; 3 blocks/SM.
// ---------------------------------------------------------------------------
#define KT 32
#define QT 32
#define KSLD 196
#define ATTN_Q_FL   (32 * 192)
#define ATTN_K_FL   (32 * KSLD)
#define ATTN_V_FL   (32 * 128)
#define ATTN_P_FL   (8 * 4 * 32)
#define ATTN_SMEM_BYTES ((ATTN_Q_FL + ATTN_K_FL + ATTN_V_FL + ATTN_P_FL + 512) * 4)

__global__ __launch_bounds__(256, 3)
void attn_kernel(const float* __restrict__ qc, const float* __restrict__ kc,
                 const float* __restrict__ vc, const float* __restrict__ qr,
                 const float* __restrict__ kr, float* __restrict__ ao) {
    extern __shared__ float smem[];
    float* Qs = smem;                          // [32][192]
    float* Ks = Qs + ATTN_Q_FL;                // [32][196]
    float* Vs = Ks + ATTN_K_FL;                // [32][128]
    float* Ps = Vs + ATTN_V_FL;                // [8][4][32]
    int* keys_sm = (int*)(Ps + ATTN_P_FL);     // [512]

    const int tid  = threadIdx.x;
    const int lane = tid & 31;
    const int warp = tid >> 5;
    const int q0 = blockIdx.x * QT;
    const int h  = blockIdx.y;
    const int b  = blockIdx.z;

    // --- enumerate candidate keys (disjoint: global | dilated | window) ---
    int lo   = max(0, q0 - WINDOW_HALF);
    int aEnd = min(lo, GLOBAL_);
    int nB   = (lo > GLOBAL_) ? (((lo - 1) >> 6) - 1) : 0;
    int hi   = q0 + QT - 1;
    int nW   = hi - lo + 1;
    int cnt  = aEnd + nB + nW;
    int cntPad = (cnt + KT - 1) & ~(KT - 1);
    for (int s = tid; s < cntPad; s += 256) {
        int k;
        if (s < aEnd)           k = s;
        else if (s < aEnd + nB) k = GLOBAL_ + 64 * (s - aEnd);
        else if (s < cnt)       k = lo + (s - aEnd - nB);
        else                    k = -1;
        keys_sm[s] = k;
    }

    const float* qc_base = qc + ((size_t)b * T_) * D_ + h * DH_;
    const float* qr_base = qr + ((size_t)b * T_) * (H_ * DR_) + h * DR_;
    const float* kc_base = kc + ((size_t)b * T_) * D_ + h * DH_;
    const float* kr_base = kr + ((size_t)b * T_) * (H_ * DR_) + h * DR_;
    const float* vc_base = vc + ((size_t)b * T_) * D_ + h * DH_;

    // --- stage pre-scaled Q tile: [0,128)=qc*SCALE ; [128,192)=qr*SCALE_ROPE
    for (int idx = tid; idx < 32 * 48; idx += 256) {
        int r = idx / 48, j = idx - r * 48;
        float4 v;
        float sc;
        if (j < 32) { v = *(const float4*)(qc_base + (size_t)(q0 + r) * D_ + 4 * j); sc = SCALE_CF; }
        else        { v = *(const float4*)(qr_base + (size_t)(q0 + r) * (H_*DR_) + 4 * (j - 32)); sc = SCALE_ROPE_CF; }
        v.x *= sc; v.y *= sc; v.z *= sc; v.w *= sc;
        *(float4*)(Qs + r * 192 + 4 * j) = v;
    }

    float m[4], l[4];
    float4 acc[4];
#pragma unroll
    for (int i = 0; i < 4; i++) {
        m[i] = -INFINITY; l[i] = 0.f;
        acc[i] = make_float4(0.f, 0.f, 0.f, 0.f);
    }

    __syncthreads();

    const float4* Q4[4];
#pragma unroll
    for (int i = 0; i < 4; i++) Q4[i] = (const float4*)(Qs + (warp * 4 + i) * 192);

    for (int s0 = 0; s0 < cntPad; s0 += KT) {
        // ---- stage K (192 f/key) and V (128 f/key) tiles, float4 ----
        for (int idx = tid; idx < 32 * 48; idx += 256) {
            int r = idx / 48, j = idx - r * 48;
            int kid = keys_sm[s0 + r];
            int krow = kid < 0 ? 0 : kid;
            float4 v;
            if (j < 32) v = *(const float4*)(kc_base + (size_t)krow * D_ + 4 * j);
            else        v = *(const float4*)(kr_base + (size_t)krow * (H_*DR_) + 4 * (j - 32));
            *(float4*)(Ks + r * KSLD + 4 * j) = v;
        }
        for (int idx = tid; idx < 32 * 32; idx += 256) {
            int r = idx >> 5, j = idx & 31;
            int kid = keys_sm[s0 + r];
            int krow = kid < 0 ? 0 : kid;
            *(float4*)(Vs + r * 128 + 4 * j) =
                *(const float4*)(vc_base + (size_t)krow * D_ + 4 * j);
        }
        __syncthreads();

        // ---- scores: lane's key vs warp's 4 queries (no shuffles) ----
        int myk = keys_sm[s0 + lane];
        const float4* Krow = (const float4*)(Ks + lane * KSLD);
        float sc0 = 0.f, sc1 = 0.f, sc2 = 0.f, sc3 = 0.f;
#pragma unroll 8
        for (int dv = 0; dv < 48; dv++) {
            float4 k4 = Krow[dv];
            float4 a;
            a = Q4[0][dv]; sc0 += k4.x*a.x + k4.y*a.y + k4.z*a.z + k4.w*a.w;
            a = Q4[1][dv]; sc1 += k4.x*a.x + k4.y*a.y + k4.z*a.z + k4.w*a.w;
            a = Q4[2][dv]; sc2 += k4.x*a.x + k4.y*a.y + k4.z*a.z + k4.w*a.w;
            a = Q4[3][dv]; sc3 += k4.x*a.x + k4.y*a.y + k4.z*a.z + k4.w*a.w;
        }
        float sc[4] = {sc0, sc1, sc2, sc3};

        // ---- mask + online softmax per query; write p to smem ----
#pragma unroll
        for (int i = 0; i < 4; i++) {
            int q = q0 + warp * 4 + i;
            bool valid = (myk >= 0) & (myk <= q) &&
                         ((q - myk) <= WINDOW_HALF || myk < GLOBAL_ ||
                          (myk & (STRIDE_ - 1)) == 0);
            float si = valid ? sc[i] : -INFINITY;
            float mx = si;
#pragma unroll
            for (int off = 16; off; off >>= 1)
                mx = fmaxf(mx, __shfl_xor_sync(0xffffffffu, mx, off));
            float mnew = fmaxf(m[i], mx);
            float corr = __expf(m[i] - mnew);          // exp(-inf)=0 on first tile
            float p = __expf(si - mnew);
            float ps = p;
#pragma unroll
            for (int off = 16; off; off >>= 1)
                ps += __shfl_xor_sync(0xffffffffu, ps, off);
            l[i] = l[i] * corr + ps;
            m[i] = mnew;
            acc[i].x *= corr; acc[i].y *= corr; acc[i].z *= corr; acc[i].w *= corr;
            Ps[warp * 128 + i * 32 + lane] = p;
        }
        __syncwarp();

        // ---- accumulate V: lane owns dims [4*lane, 4*lane+4) ----
        const float4* V4 = (const float4*)Vs;
        const float* Pw = Ps + warp * 128;
#pragma unroll 4
        for (int u = 0; u < 32; u++) {
            float4 v4 = V4[u * 32 + lane];
            float p0 = Pw[u];
            float p1 = Pw[32 + u];
            float p2 = Pw[64 + u];
            float p3 = Pw[96 + u];
            acc[0].x += p0 * v4.x; acc[0].y += p0 * v4.y; acc[0].z += p0 * v4.z; acc[0].w += p0 * v4.w;
            acc[1].x += p1 * v4.x; acc[1].y += p1 * v4.y; acc[1].z += p1 * v4.z; acc[1].w += p1 * v4.w;
            acc[2].x += p2 * v4.x; acc[2].y += p2 * v4.y; acc[2].z += p2 * v4.z; acc[2].w += p2 * v4.w;
            acc[3].x += p3 * v4.x; acc[3].y += p3 * v4.y; acc[3].z += p3 * v4.z; acc[3].w += p3 * v4.w;
        }
        __syncthreads();
    }

    // ---- epilogue: lane writes its 4 dims of each query ----
    float* ao_base = ao + ((size_t)b * T_) * D_ + h * DH_;
#pragma unroll
    for (int i = 0; i < 4; i++) {
        int q = q0 + warp * 4 + i;
        float inv_l = 1.0f / l[i];
        float4 o = make_float4(acc[i].x * inv_l, acc[i].y * inv_l,
                               acc[i].z * inv_l, acc[i].w * inv_l);
        *(float4*)(ao_base + (size_t)q * D_ + 4 * lane) = o;
    }
}

// ---------------------------------------------------------------------------
// Launch
// ---------------------------------------------------------------------------
extern "C" void kernel_launch(void* const* d_in, const int* in_sizes, int n_in,
                              void* d_out, int out_size) {
    (void)in_sizes; (void)n_in; (void)out_size;
    const float* x     = (const float*)d_in[0];
    const float* w_q   = (const float*)d_in[1];
    const float* w_dkv = (const float*)d_in[2];
    const float* w_uk  = (const float*)d_in[3];
    const float* w_uv  = (const float*)d_in[4];
    const float* w_qp  = (const float*)d_in[5];
    const float* w_kp  = (const float*)d_in[6];
    const float* w_o   = (const float*)d_in[7];
    float* out = (float*)d_out;

    float *qc, *ckv, *kc, *vc, *qr, *kr, *ao;
    cudaGetSymbolAddress((void**)&qc,  g_qc);
    cudaGetSymbolAddress((void**)&ckv, g_ckv);
    cudaGetSymbolAddress((void**)&kc,  g_kc);
    cudaGetSymbolAddress((void**)&vc,  g_vc);
    cudaGetSymbolAddress((void**)&qr,  g_qr);
    cudaGetSymbolAddress((void**)&kr,  g_kr);
    cudaGetSymbolAddress((void**)&ao,  g_ao);

    cudaFuncSetAttribute(sgemm_tf32, cudaFuncAttributeMaxDynamicSharedMemorySize,
                         GEMM_SMEM_BYTES);
    cudaFuncSetAttribute(attn_kernel, cudaFuncAttributeMaxDynamicSharedMemorySize,
                         ATTN_SMEM_BYTES);

    // projections (tensor-core 3xTF32, double-buffered)
    sgemm_tf32<<<dim3(D_ / BN, MT / BM), 256, GEMM_SMEM_BYTES>>>(x,   w_q,   qc,  MT, D_,  D_);
    sgemm_tf32<<<dim3(DL_ / BN, MT / BM), 256, GEMM_SMEM_BYTES>>>(x,  w_dkv, ckv, MT, DL_, D_);
    sgemm_tf32<<<dim3(D_ / BN, MT / BM), 256, GEMM_SMEM_BYTES>>>(ckv, w_uk,  kc,  MT, D_,  DL_);
    sgemm_tf32<<<dim3(D_ / BN, MT / BM), 256, GEMM_SMEM_BYTES>>>(ckv, w_uv,  vc,  MT, D_,  DL_);
    sgemm_tf32<<<dim3((H_ * DR_) / BN, MT / BM), 256, GEMM_SMEM_BYTES>>>(x, w_qp, qr, MT, H_ * DR_, D_);
    sgemm_tf32<<<dim3((H_ * DR_) / BN, MT / BM), 256, GEMM_SMEM_BYTES>>>(x, w_kp, kr, MT, H_ * DR_, D_);

    // rope (in place)
    int ropeThreads = MT * H_ * (DR_ / 2);
    rope_kernel<<<ropeThreads / 256, 256>>>(qr);
    rope_kernel<<<ropeThreads / 256, 256>>>(kr);

    // sparse attention
    attn_kernel<<<dim3(T_ / QT, H_, B_), 256, ATTN_SMEM_BYTES>>>(qc, kc, vc, qr, kr, ao);

    // output projection
    sgemm_tf32<<<dim3(D_ / BN, MT / BM), 256, GEMM_SMEM_BYTES>>>(ao, w_o, out, MT, D_, D_);
}

// round 14
// speedup vs baseline: 1.2371x; 1.0698x over previous
#include <cuda_runtime.h>
#include <cuda_bf16.h>
#include <mma.h>
#include <math.h>
#include <stdint.h>

using namespace nvcuda;

// ---------------------------------------------------------------------------
// Problem constants
// ---------------------------------------------------------------------------
#define B_ 2
#define T_ 2048
#define D_ 2048
#define H_ 16
#define DH_ 128
#define DR_ 64
#define DL_ 512
#define WINDOW_HALF 256
#define STRIDE_ 64
#define GLOBAL_ 128
#define SCALE_CF      0.08838834764831845f   // 1/sqrt(128)
#define SCALE_ROPE_CF 0.125f                 // 1/sqrt(64)
#define YARN_F 1.3465735902799727f  // 0.1*ln(32)+1
#define LOG2_10000 13.287712379549449f

#define MT (B_*T_)            // 4096 rows

// ---------------------------------------------------------------------------
// Scratch (device globals; no allocation allowed)
// ---------------------------------------------------------------------------
__device__ float g_qc [(size_t)MT * D_];          // [4096,2048]
__device__ float g_ckv[(size_t)MT * DL_];         // [4096,512]
__device__ float g_kc [(size_t)MT * D_];
__device__ float g_vc [(size_t)MT * D_];
__device__ float g_qr [(size_t)MT * (H_*DR_)];    // [4096,1024]
__device__ float g_kr [(size_t)MT * (H_*DR_)];
__device__ float g_ao [(size_t)MT * D_];

// ---------------------------------------------------------------------------
// 3xTF32 tensor-core GEMM core (measured: 342us @ 2048^3, tensor=50%).
// Block tile 128x128x16, 8 warps, warp tile 64x32; double-buffered smem.
// ---------------------------------------------------------------------------
#define BM 128
#define BN 128
#define BKT 16
#define ALD 20
#define BLD 132

#define A_FL (BM * ALD)
#define B_FL (BKT * BLD)
#define STG_FL (2 * A_FL + 2 * B_FL)
#define GEMM_SMEM_BYTES (2 * STG_FL * 4)

__device__ __forceinline__ void split_tf32(float v, float* __restrict__ hi,
                                           float* __restrict__ lo) {
    float h = wmma::__float_to_tf32(v);
    *hi = h;
    *lo = wmma::__float_to_tf32(v - h);
}

// Ab: A + blockRow*128*K ; Bb: W + colOffset ; Cb: C + blockRow*128*ld + col.
__device__ __forceinline__ void gemm_core_128(const float* __restrict__ Ab,
                                              const float* __restrict__ Bb,
                                              float* __restrict__ Cb,
                                              int K, int ld, float* smem) {
    const int tid  = threadIdx.x;
    const int warp = tid >> 5;
    const int wr = warp >> 2;
    const int wc = warp & 3;

    const int idx0 = tid * 2;
    const int aR0 = idx0 >> 2,        aC0 = (idx0 & 3) * 4;
    const int aR1 = (idx0 + 1) >> 2,  aC1 = ((idx0 + 1) & 3) * 4;
    const int bR0 = idx0 >> 5,        bC0 = (idx0 & 31) * 4;
    const int bR1 = (idx0 + 1) >> 5,  bC1 = ((idx0 + 1) & 31) * 4;

    wmma::fragment<wmma::accumulator, 16, 16, 8, float> acc[4][2];
#pragma unroll
    for (int i = 0; i < 4; i++)
#pragma unroll
        for (int j = 0; j < 2; j++) wmma::fill_fragment(acc[i][j], 0.0f);

    const int nIter = K / BKT;

    auto stage_store = [&](int s, const float4& a0, const float4& a1,
                           const float4& b0, const float4& b1) {
        float* Ah = smem + s * STG_FL;
        float* Al = Ah + A_FL;
        float* Bh = Al + A_FL;
        float* Bl = Bh + B_FL;
        split_tf32(a0.x, &Ah[aR0*ALD + aC0+0], &Al[aR0*ALD + aC0+0]);
        split_tf32(a0.y, &Ah[aR0*ALD + aC0+1], &Al[aR0*ALD + aC0+1]);
        split_tf32(a0.z, &Ah[aR0*ALD + aC0+2], &Al[aR0*ALD + aC0+2]);
        split_tf32(a0.w, &Ah[aR0*ALD + aC0+3], &Al[aR0*ALD + aC0+3]);
        split_tf32(a1.x, &Ah[aR1*ALD + aC1+0], &Al[aR1*ALD + aC1+0]);
        split_tf32(a1.y, &Ah[aR1*ALD + aC1+1], &Al[aR1*ALD + aC1+1]);
        split_tf32(a1.z, &Ah[aR1*ALD + aC1+2], &Al[aR1*ALD + aC1+2]);
        split_tf32(a1.w, &Ah[aR1*ALD + aC1+3], &Al[aR1*ALD + aC1+3]);
        split_tf32(b0.x, &Bh[bR0*BLD + bC0+0], &Bl[bR0*BLD + bC0+0]);
        split_tf32(b0.y, &Bh[bR0*BLD + bC0+1], &Bl[bR0*BLD + bC0+1]);
        split_tf32(b0.z, &Bh[bR0*BLD + bC0+2], &Bl[bR0*BLD + bC0+2]);
        split_tf32(b0.w, &Bh[bR0*BLD + bC0+3], &Bl[bR0*BLD + bC0+3]);
        split_tf32(b1.x, &Bh[bR1*BLD + bC1+0], &Bl[bR1*BLD + bC1+0]);
        split_tf32(b1.y, &Bh[bR1*BLD + bC1+1], &Bl[bR1*BLD + bC1+1]);
        split_tf32(b1.z, &Bh[bR1*BLD + bC1+2], &Bl[bR1*BLD + bC1+2]);
        split_tf32(b1.w, &Bh[bR1*BLD + bC1+3], &Bl[bR1*BLD + bC1+3]);
    };

    {
        float4 a0 = *(const float4*)(Ab + (size_t)aR0 * K + aC0);
        float4 a1 = *(const float4*)(Ab + (size_t)aR1 * K + aC1);
        float4 b0 = *(const float4*)(Bb + (size_t)bR0 * ld + bC0);
        float4 b1 = *(const float4*)(Bb + (size_t)bR1 * ld + bC1);
        stage_store(0, a0, a1, b0, b1);
    }
    __syncthreads();

    int cur = 0;
    for (int kt = 0; kt < nIter; kt++) {
        float4 a0, a1, b0, b1;
        const bool has = (kt + 1) < nIter;
        if (has) {
            int k0 = (kt + 1) * BKT;
            a0 = *(const float4*)(Ab + (size_t)aR0 * K + k0 + aC0);
            a1 = *(const float4*)(Ab + (size_t)aR1 * K + k0 + aC1);
            b0 = *(const float4*)(Bb + (size_t)(k0 + bR0) * ld + bC0);
            b1 = *(const float4*)(Bb + (size_t)(k0 + bR1) * ld + bC1);
        }

        const float* Ah = smem + cur * STG_FL;
        const float* Al = Ah + A_FL;
        const float* Bh = Al + A_FL;
        const float* Bl = Bh + B_FL;

#pragma unroll
        for (int ks = 0; ks < 2; ks++) {
            wmma::fragment<wmma::matrix_a, 16, 16, 8, wmma::precision::tf32, wmma::row_major> fah[4], fal[4];
#pragma unroll
            for (int i = 0; i < 4; i++) {
                wmma::load_matrix_sync(fah[i], &Ah[(wr * 64 + i * 16) * ALD + ks * 8], ALD);
                wmma::load_matrix_sync(fal[i], &Al[(wr * 64 + i * 16) * ALD + ks * 8], ALD);
            }
#pragma unroll
            for (int j = 0; j < 2; j++) {
                wmma::fragment<wmma::matrix_b, 16, 16, 8, wmma::precision::tf32, wmma::row_major> fbh, fbl;
                wmma::load_matrix_sync(fbh, &Bh[(ks * 8) * BLD + wc * 32 + j * 16], BLD);
                wmma::load_matrix_sync(fbl, &Bl[(ks * 8) * BLD + wc * 32 + j * 16], BLD);
#pragma unroll
                for (int i = 0; i < 4; i++) {
                    wmma::mma_sync(acc[i][j], fah[i], fbh, acc[i][j]);
                    wmma::mma_sync(acc[i][j], fal[i], fbh, acc[i][j]);
                    wmma::mma_sync(acc[i][j], fah[i], fbl, acc[i][j]);
                }
            }
        }

        if (has) stage_store(cur ^ 1, a0, a1, b0, b1);
        __syncthreads();
        cur ^= 1;
    }

#pragma unroll
    for (int i = 0; i < 4; i++)
#pragma unroll
        for (int j = 0; j < 2; j++)
            wmma::store_matrix_sync(Cb + (size_t)(wr * 64 + i * 16) * ld + wc * 32 + j * 16,
                                    acc[i][j], ld, wmma::mem_row_major);
}

// ---------------------------------------------------------------------------
// Launch [0]: all four x-consuming projections in ONE kernel.
// grid.x = 36 N-tiles: [0,16)=w_q->qc, [16,20)=w_dkv->ckv,
// [20,28)=w_qp->qr, [28,36)=w_kp->kr. grid.y = 32 M-tiles.
// ---------------------------------------------------------------------------
__global__ __launch_bounds__(256, 2)
void xproj_kernel(const float* __restrict__ x,
                  const float* __restrict__ w_q, const float* __restrict__ w_dkv,
                  const float* __restrict__ w_qp, const float* __restrict__ w_kp,
                  float* __restrict__ qc, float* __restrict__ ckv,
                  float* __restrict__ qr, float* __restrict__ kr) {
    extern __shared__ float smem[];
    int bx = blockIdx.x, by = blockIdx.y;
    const float* W; float* C; int ld, col;
    if (bx < 16)      { W = w_q;   C = qc;  ld = D_;      col = bx * 128; }
    else if (bx < 20) { W = w_dkv; C = ckv; ld = DL_;     col = (bx - 16) * 128; }
    else if (bx < 28) { W = w_qp;  C = qr;  ld = H_ * DR_; col = (bx - 20) * 128; }
    else              { W = w_kp;  C = kr;  ld = H_ * DR_; col = (bx - 28) * 128; }
    gemm_core_128(x + (size_t)(by * BM) * D_, W + col,
                  C + (size_t)(by * BM) * ld + col, D_, ld, smem);
}

// ---------------------------------------------------------------------------
// Launch [1]: uk/uv GEMMs (z=0/1) + YaRN rope for qr & kr (z=2 slice).
// grid (16, 32, 3).
// ---------------------------------------------------------------------------
__global__ __launch_bounds__(256, 2)
void ukuv_rope_kernel(const float* __restrict__ ckv,
                      const float* __restrict__ w_uk, const float* __restrict__ w_uv,
                      float* __restrict__ kc, float* __restrict__ vc,
                      float* __restrict__ qr, float* __restrict__ kr) {
    extern __shared__ float smem[];
    int z = blockIdx.z;
    if (z < 2) {
        const float* W = z ? w_uv : w_uk;
        float* C = z ? vc : kc;
        int bx = blockIdx.x, by = blockIdx.y;
        gemm_core_128(ckv + (size_t)(by * BM) * DL_, W + bx * 128,
                      C + (size_t)(by * BM) * D_ + bx * 128, DL_, D_, smem);
        return;
    }
    // rope: grid-stride over both buffers; pairs total = 2 * MT*H*DR/2 = 2^22
    const int nThreads = 16 * 32 * 256;                 // 131072
    int tg = (blockIdx.y * 16 + blockIdx.x) * 256 + threadIdx.x;
    for (int p = tg; p < 2 * MT * H_ * (DR_ / 2); p += nThreads) {
        float* buf = (p < MT * H_ * (DR_ / 2)) ? qr : kr;
        int pp = p & (MT * H_ * (DR_ / 2) - 1);
        int i  = pp & 31;
        int h  = (pp >> 5) & (H_ - 1);
        int bt = pp >> 9;
        int t = bt & (T_ - 1);

        float fi = (float)i;
        float base_inv = exp2f(-(2.0f * fi / 64.0f) * LOG2_10000);
        float ramp = fminf(fmaxf((fi - 1.0f) / 31.0f, 0.0f), 1.0f);
        float inv = base_inv * (1.0f - ramp) + (base_inv * (1.0f / 32.0f)) * ramp;
        float fr = (float)t * inv;
        float c = cosf(fr) * YARN_F;
        float s = sinf(fr) * YARN_F;

        size_t base = (size_t)bt * (H_ * DR_) + h * DR_;
        float x1 = buf[base + i];
        float x2 = buf[base + i + 32];
        buf[base + i]      = x1 * c - x2 * s;
        buf[base + i + 32] = x2 * c + x1 * s;
    }
}

// ---------------------------------------------------------------------------
// Launch [4]: output projection.
// ---------------------------------------------------------------------------
__global__ __launch_bounds__(256, 2)
void wo_kernel(const float* __restrict__ ao, const float* __restrict__ w_o,
               float* __restrict__ out) {
    extern __shared__ float smem[];
    int bx = blockIdx.x, by = blockIdx.y;
    gemm_core_128(ao + (size_t)(by * BM) * D_, w_o + bx * 128,
                  out + (size_t)(by * BM) * D_ + bx * 128, D_, D_, smem);
}

// ---------------------------------------------------------------------------
// Sparse attention (one batch per launch; grid (64, 16)).
// Shuffle-free float4 layout + SOFTWARE-PIPELINED staging: next tile's K/V
// gather LDGs issued into registers before computing the current tile;
// STS after the read barrier. 2 barriers/tile, gather latency hidden.
// ---------------------------------------------------------------------------
#define KT 32
#define QT 32
#define KSLD 196
#define ATTN_Q_FL   (32 * 192)
#define ATTN_K_FL   (32 * KSLD)
#define ATTN_V_FL   (32 * 128)
#define ATTN_P_FL   (8 * 4 * 32)
#define ATTN_SMEM_BYTES ((ATTN_Q_FL + ATTN_K_FL + ATTN_V_FL + ATTN_P_FL + 512) * 4)

__global__ __launch_bounds__(256, 2)
void attn_kernel(const float* __restrict__ qc, const float* __restrict__ kc,
                 const float* __restrict__ vc, const float* __restrict__ qr,
                 const float* __restrict__ kr, float* __restrict__ ao,
                 int batch) {
    extern __shared__ float smem[];
    float* Qs = smem;                          // [32][192]
    float* Ks = Qs + ATTN_Q_FL;                // [32][196]
    float* Vs = Ks + ATTN_K_FL;                // [32][128]
    float* Ps = Vs + ATTN_V_FL;                // [8][4][32]
    int* keys_sm = (int*)(Ps + ATTN_P_FL);     // [512]

    const int tid  = threadIdx.x;
    const int lane = tid & 31;
    const int warp = tid >> 5;
    const int q0 = blockIdx.x * QT;
    const int h  = blockIdx.y;
    const int b  = batch;

    // --- enumerate candidate keys (disjoint: global | dilated | window) ---
    int lo   = max(0, q0 - WINDOW_HALF);
    int aEnd = min(lo, GLOBAL_);
    int nB   = (lo > GLOBAL_) ? (((lo - 1) >> 6) - 1) : 0;
    int hi   = q0 + QT - 1;
    int nW   = hi - lo + 1;
    int cnt  = aEnd + nB + nW;
    int cntPad = (cnt + KT - 1) & ~(KT - 1);
    for (int s = tid; s < cntPad; s += 256) {
        int k;
        if (s < aEnd)           k = s;
        else if (s < aEnd + nB) k = GLOBAL_ + 64 * (s - aEnd);
        else if (s < cnt)       k = lo + (s - aEnd - nB);
        else                    k = -1;
        keys_sm[s] = k;
    }

    const float* qc_base = qc + ((size_t)b * T_) * D_ + h * DH_;
    const float* qr_base = qr + ((size_t)b * T_) * (H_ * DR_) + h * DR_;
    const float* kc_base = kc + ((size_t)b * T_) * D_ + h * DH_;
    const float* kr_base = kr + ((size_t)b * T_) * (H_ * DR_) + h * DR_;
    const float* vc_base = vc + ((size_t)b * T_) * D_ + h * DH_;

    // per-thread staging coordinates (fixed across tiles)
    const int kR[6] = { tid / 48, (tid + 256) / 48, (tid + 512) / 48,
                        (tid + 768) / 48, (tid + 1024) / 48, (tid + 1280) / 48 };
    const int kJ[6] = { tid % 48, (tid + 256) % 48, (tid + 512) % 48,
                        (tid + 768) % 48, (tid + 1024) % 48, (tid + 1280) % 48 };
    // V: idx = tid + it*256 ; r = idx>>5 ; j = idx&31 (j constant = tid&31)
    const int vJ = tid & 31;

    // gather one tile's worth for this thread into regs
    auto gather_tile = [&](int s0, float4* kp, float4* vp) {
#pragma unroll
        for (int it = 0; it < 6; it++) {
            int kid = keys_sm[s0 + kR[it]];
            int krow = kid < 0 ? 0 : kid;
            int j = kJ[it];
            kp[it] = (j < 32)
                ? *(const float4*)(kc_base + (size_t)krow * D_ + 4 * j)
                : *(const float4*)(kr_base + (size_t)krow * (H_*DR_) + 4 * (j - 32));
        }
#pragma unroll
        for (int it = 0; it < 4; it++) {
            int r = (tid + it * 256) >> 5;
            int kid = keys_sm[s0 + r];
            int krow = kid < 0 ? 0 : kid;
            vp[it] = *(const float4*)(vc_base + (size_t)krow * D_ + 4 * vJ);
        }
    };
    auto store_tile = [&](const float4* kp, const float4* vp) {
#pragma unroll
        for (int it = 0; it < 6; it++)
            *(float4*)(Ks + kR[it] * KSLD + 4 * kJ[it]) = kp[it];
#pragma unroll
        for (int it = 0; it < 4; it++) {
            int r = (tid + it * 256) >> 5;
            *(float4*)(Vs + r * 128 + 4 * vJ) = vp[it];
        }
    };

    // --- stage pre-scaled Q tile: [0,128)=qc*SCALE ; [128,192)=qr*SCALE_ROPE
#pragma unroll
    for (int it = 0; it < 6; it++) {
        int r = kR[it], j = kJ[it];
        float4 v;
        float sc;
        if (j < 32) { v = *(const float4*)(qc_base + (size_t)(q0 + r) * D_ + 4 * j); sc = SCALE_CF; }
        else        { v = *(const float4*)(qr_base + (size_t)(q0 + r) * (H_*DR_) + 4 * (j - 32)); sc = SCALE_ROPE_CF; }
        v.x *= sc; v.y *= sc; v.z *= sc; v.w *= sc;
        *(float4*)(Qs + r * 192 + 4 * j) = v;
    }

    // keys_sm written cooperatively above; prologue gather reads slots written
    // by OTHER threads -> must fence before first use.
    __syncthreads();

    // prologue: stage tile 0
    {
        float4 kp[6], vp[4];
        gather_tile(0, kp, vp);
        // Qs writes (pre-barrier) and Ks/Vs writes are disjoint regions;
        // visibility for both ensured by the barrier below.
        store_tile(kp, vp);
    }

    float m[4], l[4];
    float4 acc[4];
#pragma unroll
    for (int i = 0; i < 4; i++) {
        m[i] = -INFINITY; l[i] = 0.f;
        acc[i] = make_float4(0.f, 0.f, 0.f, 0.f);
    }

    __syncthreads();

    const float4* Q4[4];
#pragma unroll
    for (int i = 0; i < 4; i++) Q4[i] = (const float4*)(Qs + (warp * 4 + i) * 192);

    for (int s0 = 0; s0 < cntPad; s0 += KT) {
        const bool has = (s0 + KT) < cntPad;
        float4 kp[6], vp[4];
        if (has) gather_tile(s0 + KT, kp, vp);   // LDGs in flight during compute

        // ---- scores: lane's key vs warp's 4 queries (no shuffles) ----
        int myk = keys_sm[s0 + lane];
        const float4* Krow = (const float4*)(Ks + lane * KSLD);
        float sc0 = 0.f, sc1 = 0.f, sc2 = 0.f, sc3 = 0.f;
#pragma unroll 8
        for (int dv = 0; dv < 48; dv++) {
            float4 k4 = Krow[dv];
            float4 a;
            a = Q4[0][dv]; sc0 += k4.x*a.x + k4.y*a.y + k4.z*a.z + k4.w*a.w;
            a = Q4[1][dv]; sc1 += k4.x*a.x + k4.y*a.y + k4.z*a.z + k4.w*a.w;
            a = Q4[2][dv]; sc2 += k4.x*a.x + k4.y*a.y + k4.z*a.z + k4.w*a.w;
            a = Q4[3][dv]; sc3 += k4.x*a.x + k4.y*a.y + k4.z*a.z + k4.w*a.w;
        }
        float sc[4] = {sc0, sc1, sc2, sc3};

        // ---- mask + online softmax per query; write p to smem ----
#pragma unroll
        for (int i = 0; i < 4; i++) {
            int q = q0 + warp * 4 + i;
            bool valid = (myk >= 0) & (myk <= q) &&
                         ((q - myk) <= WINDOW_HALF || myk < GLOBAL_ ||
                          (myk & (STRIDE_ - 1)) == 0);
            float si = valid ? sc[i] : -INFINITY;
            float mx = si;
#pragma unroll
            for (int off = 16; off; off >>= 1)
                mx = fmaxf(mx, __shfl_xor_sync(0xffffffffu, mx, off));
            float mnew = fmaxf(m[i], mx);
            float corr = __expf(m[i] - mnew);          // exp(-inf)=0 on first tile
            float p = __expf(si - mnew);
            float ps = p;
#pragma unroll
            for (int off = 16; off; off >>= 1)
                ps += __shfl_xor_sync(0xffffffffu, ps, off);
            l[i] = l[i] * corr + ps;
            m[i] = mnew;
            acc[i].x *= corr; acc[i].y *= corr; acc[i].z *= corr; acc[i].w *= corr;
            Ps[warp * 128 + i * 32 + lane] = p;
        }
        __syncwarp();

        // ---- accumulate V: lane owns dims [4*lane, 4*lane+4) ----
        const float4* V4 = (const float4*)Vs;
        const float* Pw = Ps + warp * 128;
#pragma unroll 4
        for (int u = 0; u < 32; u++) {
            float4 v4 = V4[u * 32 + lane];
            float p0 = Pw[u];
            float p1 = Pw[32 + u];
            float p2 = Pw[64 + u];
            float p3 = Pw[96 + u];
            acc[0].x += p0 * v4.x; acc[0].y += p0 * v4.y; acc[0].z += p0 * v4.z; acc[0].w += p0 * v4.w;
            acc[1].x += p1 * v4.x; acc[1].y += p1 * v4.y; acc[1].z += p1 * v4.z; acc[1].w += p1 * v4.w;
            acc[2].x += p2 * v4.x; acc[2].y += p2 * v4.y; acc[2].z += p2 * v4.z; acc[2].w += p2 * v4.w;
            acc[3].x += p3 * v4.x; acc[3].y += p3 * v4.y; acc[3].z += p3 * v4.z; acc[3].w += p3 * v4.w;
        }

        __syncthreads();              // all reads of Ks/Vs complete
        if (has) store_tile(kp, vp);  // STS next tile
        __syncthreads();              // staged data visible
    }

    // ---- epilogue: lane writes its 4 dims of each query ----
    float* ao_base = ao + ((size_t)b * T_) * D_ + h * DH_;
#pragma unroll
    for (int i = 0; i < 4; i++) {
        int q = q0 + warp * 4 + i;
        float inv_l = 1.0f / l[i];
        float4 o = make_float4(acc[i].x * inv_l, acc[i].y * inv_l,
                               acc[i].z * inv_l, acc[i].w * inv_l);
        *(float4*)(ao_base + (size_t)q * D_ + 4 * lane) = o;
    }
}

// ---------------------------------------------------------------------------
// Launch: [0] xproj  [1] ukuv+rope  [2] attn b0  [3] attn b1  [4] w_o
// (5 launches/replay so ncu -s 5 -c 1 lands on attention for pre-offset 2/3.)
// ---------------------------------------------------------------------------
extern "C" void kernel_launch(void* const* d_in, const int* in_sizes, int n_in,
                              void* d_out, int out_size) {
    (void)in_sizes; (void)n_in; (void)out_size;
    const float* x     = (const float*)d_in[0];
    const float* w_q   = (const float*)d_in[1];
    const float* w_dkv = (const float*)d_in[2];
    const float* w_uk  = (const float*)d_in[3];
    const float* w_uv  = (const float*)d_in[4];
    const float* w_qp  = (const float*)d_in[5];
    const float* w_kp  = (const float*)d_in[6];
    const float* w_o   = (const float*)d_in[7];
    float* out = (float*)d_out;

    float *qc, *ckv, *kc, *vc, *qr, *kr, *ao;
    cudaGetSymbolAddress((void**)&qc,  g_qc);
    cudaGetSymbolAddress((void**)&ckv, g_ckv);
    cudaGetSymbolAddress((void**)&kc,  g_kc);
    cudaGetSymbolAddress((void**)&vc,  g_vc);
    cudaGetSymbolAddress((void**)&qr,  g_qr);
    cudaGetSymbolAddress((void**)&kr,  g_kr);
    cudaGetSymbolAddress((void**)&ao,  g_ao);

    cudaFuncSetAttribute(xproj_kernel, cudaFuncAttributeMaxDynamicSharedMemorySize,
                         GEMM_SMEM_BYTES);
    cudaFuncSetAttribute(ukuv_rope_kernel, cudaFuncAttributeMaxDynamicSharedMemorySize,
                         GEMM_SMEM_BYTES);
    cudaFuncSetAttribute(wo_kernel, cudaFuncAttributeMaxDynamicSharedMemorySize,
                         GEMM_SMEM_BYTES);
    cudaFuncSetAttribute(attn_kernel, cudaFuncAttributeMaxDynamicSharedMemorySize,
                         ATTN_SMEM_BYTES);

    // [0] all x-projections (qc, ckv, qr, kr)
    xproj_kernel<<<dim3(36, 32), 256, GEMM_SMEM_BYTES>>>(
        x, w_q, w_dkv, w_qp, w_kp, qc, ckv, qr, kr);

    // [1] uk/uv GEMMs + rope(qr, kr)
    ukuv_rope_kernel<<<dim3(16, 32, 3), 256, GEMM_SMEM_BYTES>>>(
        ckv, w_uk, w_uv, kc, vc, qr, kr);

    // [2],[3] sparse attention per batch
    attn_kernel<<<dim3(T_ / QT, H_), 256, ATTN_SMEM_BYTES>>>(qc, kc, vc, qr, kr, ao, 0);
    attn_kernel<<<dim3(T_ / QT, H_), 256, ATTN_SMEM_BYTES>>>(qc, kc, vc, qr, kr, ao, 1);

    // [4] output projection
    wo_kernel<<<dim3(16, 32), 256, GEMM_SMEM_BYTES>>>(ao, w_o, out);
}

// round 16
// speedup vs baseline: 2.7983x; 2.2620x over previous
#include <cuda_runtime.h>
#include <cuda_bf16.h>
#include <mma.h>
#include <math.h>
#include <stdint.h>

using namespace nvcuda;

// ---------------------------------------------------------------------------
// Problem constants
// ---------------------------------------------------------------------------
#define B_ 2
#define T_ 2048
#define D_ 2048
#define H_ 16
#define DH_ 128
#define DR_ 64
#define DL_ 512
#define WINDOW_HALF 256
#define STRIDE_ 64
#define GLOBAL_ 128
#define SCALE_CF      0.08838834764831845f   // 1/sqrt(128)
#define SCALE_ROPE_CF 0.125f                 // 1/sqrt(64)
#define YARN_F 1.3465735902799727f  // 0.1*ln(32)+1
#define LOG2_10000 13.287712379549449f

#define MT (B_*T_)            // 4096 rows

// ---------------------------------------------------------------------------
// Scratch (device globals; no allocation allowed)
// ---------------------------------------------------------------------------
__device__ float g_qc [(size_t)MT * D_];          // [4096,2048]
__device__ float g_ckv[(size_t)MT * DL_];         // [4096,512]
__device__ float g_kc [(size_t)MT * D_];
__device__ float g_vc [(size_t)MT * D_];
__device__ float g_qr [(size_t)MT * (H_*DR_)];    // [4096,1024]
__device__ float g_kr [(size_t)MT * (H_*DR_)];
__device__ float g_ao [(size_t)MT * D_];

// ---------------------------------------------------------------------------
// 2xBF16-split tensor-core GEMM core (3 products: AhBh + AlBh + AhBl).
// wmma m16n16k16 bf16, fp32 accumulate. Block tile 128x128x16, 8 warps,
// warp tile 64x32; double-buffered smem; same proven pipeline structure.
// ---------------------------------------------------------------------------
#define BM 128
#define BN 128
#define BKT 16
#define ALD 24     // bf16 A leading dim (16 + 8 pad), mult of 8
#define BLD 136    // bf16 B leading dim (128 + 8 pad), mult of 8

#define A_EL (BM * ALD)              // 3072 bf16
#define B_EL (BKT * BLD)             // 2176 bf16
#define STG_EL (2 * A_EL + 2 * B_EL) // 10496 bf16 per stage
#define GEMM_SMEM_BYTES (2 * STG_EL * 2)   // 41984 bytes

// split v = hi + lo (bf16 each) and store 4 consecutive elements at idx.
__device__ __forceinline__ void split_store4(__nv_bfloat16* __restrict__ hi,
                                             __nv_bfloat16* __restrict__ lo,
                                             int idx, float4 v) {
    __nv_bfloat16 hx = __float2bfloat16(v.x);
    __nv_bfloat16 hy = __float2bfloat16(v.y);
    __nv_bfloat16 hz = __float2bfloat16(v.z);
    __nv_bfloat16 hw = __float2bfloat16(v.w);
    __nv_bfloat16 lx = __float2bfloat16(v.x - __bfloat162float(hx));
    __nv_bfloat16 ly = __float2bfloat16(v.y - __bfloat162float(hy));
    __nv_bfloat16 lz = __float2bfloat16(v.z - __bfloat162float(hz));
    __nv_bfloat16 lw = __float2bfloat16(v.w - __bfloat162float(hw));
    *(__nv_bfloat162*)(hi + idx)     = __halves2bfloat162(hx, hy);
    *(__nv_bfloat162*)(hi + idx + 2) = __halves2bfloat162(hz, hw);
    *(__nv_bfloat162*)(lo + idx)     = __halves2bfloat162(lx, ly);
    *(__nv_bfloat162*)(lo + idx + 2) = __halves2bfloat162(lz, lw);
}

// Ab: A + blockRow*128*K ; Bb: W + colOffset ; Cb: C + blockRow*128*ld + col.
__device__ __forceinline__ void gemm_core_128(const float* __restrict__ Ab,
                                              const float* __restrict__ Bb,
                                              float* __restrict__ Cb,
                                              int K, int ld, float* smem_f) {
    __nv_bfloat16* smem = (__nv_bfloat16*)smem_f;
    const int tid  = threadIdx.x;
    const int warp = tid >> 5;
    const int wr = warp >> 2;
    const int wc = warp & 3;

    const int idx0 = tid * 2;
    const int aR0 = idx0 >> 2,        aC0 = (idx0 & 3) * 4;
    const int aR1 = (idx0 + 1) >> 2,  aC1 = ((idx0 + 1) & 3) * 4;
    const int bR0 = idx0 >> 5,        bC0 = (idx0 & 31) * 4;
    const int bR1 = (idx0 + 1) >> 5,  bC1 = ((idx0 + 1) & 31) * 4;

    wmma::fragment<wmma::accumulator, 16, 16, 16, float> acc[4][2];
#pragma unroll
    for (int i = 0; i < 4; i++)
#pragma unroll
        for (int j = 0; j < 2; j++) wmma::fill_fragment(acc[i][j], 0.0f);

    const int nIter = K / BKT;

    auto stage_store = [&](int s, const float4& a0, const float4& a1,
                           const float4& b0, const float4& b1) {
        __nv_bfloat16* Ah = smem + s * STG_EL;
        __nv_bfloat16* Al = Ah + A_EL;
        __nv_bfloat16* Bh = Al + A_EL;
        __nv_bfloat16* Bl = Bh + B_EL;
        split_store4(Ah, Al, aR0 * ALD + aC0, a0);
        split_store4(Ah, Al, aR1 * ALD + aC1, a1);
        split_store4(Bh, Bl, bR0 * BLD + bC0, b0);
        split_store4(Bh, Bl, bR1 * BLD + bC1, b1);
    };

    {
        float4 a0 = *(const float4*)(Ab + (size_t)aR0 * K + aC0);
        float4 a1 = *(const float4*)(Ab + (size_t)aR1 * K + aC1);
        float4 b0 = *(const float4*)(Bb + (size_t)bR0 * ld + bC0);
        float4 b1 = *(const float4*)(Bb + (size_t)bR1 * ld + bC1);
        stage_store(0, a0, a1, b0, b1);
    }
    __syncthreads();

    int cur = 0;
    for (int kt = 0; kt < nIter; kt++) {
        float4 a0, a1, b0, b1;
        const bool has = (kt + 1) < nIter;
        if (has) {
            int k0 = (kt + 1) * BKT;
            a0 = *(const float4*)(Ab + (size_t)aR0 * K + k0 + aC0);
            a1 = *(const float4*)(Ab + (size_t)aR1 * K + k0 + aC1);
            b0 = *(const float4*)(Bb + (size_t)(k0 + bR0) * ld + bC0);
            b1 = *(const float4*)(Bb + (size_t)(k0 + bR1) * ld + bC1);
        }

        const __nv_bfloat16* Ah = smem + cur * STG_EL;
        const __nv_bfloat16* Al = Ah + A_EL;
        const __nv_bfloat16* Bh = Al + A_EL;
        const __nv_bfloat16* Bl = Bh + B_EL;

        wmma::fragment<wmma::matrix_a, 16, 16, 16, __nv_bfloat16, wmma::row_major> fah[4], fal[4];
#pragma unroll
        for (int i = 0; i < 4; i++) {
            wmma::load_matrix_sync(fah[i], &Ah[(wr * 64 + i * 16) * ALD], ALD);
            wmma::load_matrix_sync(fal[i], &Al[(wr * 64 + i * 16) * ALD], ALD);
        }
#pragma unroll
        for (int j = 0; j < 2; j++) {
            wmma::fragment<wmma::matrix_b, 16, 16, 16, __nv_bfloat16, wmma::row_major> fbh, fbl;
            wmma::load_matrix_sync(fbh, &Bh[wc * 32 + j * 16], BLD);
            wmma::load_matrix_sync(fbl, &Bl[wc * 32 + j * 16], BLD);
#pragma unroll
            for (int i = 0; i < 4; i++) {
                wmma::mma_sync(acc[i][j], fah[i], fbh, acc[i][j]);
                wmma::mma_sync(acc[i][j], fal[i], fbh, acc[i][j]);
                wmma::mma_sync(acc[i][j], fah[i], fbl, acc[i][j]);
            }
        }

        if (has) stage_store(cur ^ 1, a0, a1, b0, b1);
        __syncthreads();
        cur ^= 1;
    }

#pragma unroll
    for (int i = 0; i < 4; i++)
#pragma unroll
        for (int j = 0; j < 2; j++)
            wmma::store_matrix_sync(Cb + (size_t)(wr * 64 + i * 16) * ld + wc * 32 + j * 16,
                                    acc[i][j], ld, wmma::mem_row_major);
}

// ---------------------------------------------------------------------------
// Launch [0]: all four x-consuming projections in ONE kernel.
// grid.x = 36 N-tiles: [0,16)=w_q->qc, [16,20)=w_dkv->ckv,
// [20,28)=w_qp->qr, [28,36)=w_kp->kr. grid.y = 32 M-tiles.
// ---------------------------------------------------------------------------
__global__ __launch_bounds__(256, 2)
void xproj_kernel(const float* __restrict__ x,
                  const float* __restrict__ w_q, const float* __restrict__ w_dkv,
                  const float* __restrict__ w_qp, const float* __restrict__ w_kp,
                  float* __restrict__ qc, float* __restrict__ ckv,
                  float* __restrict__ qr, float* __restrict__ kr) {
    extern __shared__ float smem[];
    int bx = blockIdx.x, by = blockIdx.y;
    const float* W; float* C; int ld, col;
    if (bx < 16)      { W = w_q;   C = qc;  ld = D_;      col = bx * 128; }
    else if (bx < 20) { W = w_dkv; C = ckv; ld = DL_;     col = (bx - 16) * 128; }
    else if (bx < 28) { W = w_qp;  C = qr;  ld = H_ * DR_; col = (bx - 20) * 128; }
    else              { W = w_kp;  C = kr;  ld = H_ * DR_; col = (bx - 28) * 128; }
    gemm_core_128(x + (size_t)(by * BM) * D_, W + col,
                  C + (size_t)(by * BM) * ld + col, D_, ld, smem);
}

// ---------------------------------------------------------------------------
// Launch [1]: uk/uv GEMMs (z=0/1) + YaRN rope for qr & kr (z=2 slice).
// grid (16, 32, 3).
// ---------------------------------------------------------------------------
__global__ __launch_bounds__(256, 2)
void ukuv_rope_kernel(const float* __restrict__ ckv,
                      const float* __restrict__ w_uk, const float* __restrict__ w_uv,
                      float* __restrict__ kc, float* __restrict__ vc,
                      float* __restrict__ qr, float* __restrict__ kr) {
    extern __shared__ float smem[];
    int z = blockIdx.z;
    if (z < 2) {
        const float* W = z ? w_uv : w_uk;
        float* C = z ? vc : kc;
        int bx = blockIdx.x, by = blockIdx.y;
        gemm_core_128(ckv + (size_t)(by * BM) * DL_, W + bx * 128,
                      C + (size_t)(by * BM) * D_ + bx * 128, DL_, D_, smem);
        return;
    }
    // rope: grid-stride over both buffers; pairs total = 2 * MT*H*DR/2 = 2^22
    const int nThreads = 16 * 32 * 256;                 // 131072
    int tg = (blockIdx.y * 16 + blockIdx.x) * 256 + threadIdx.x;
    for (int p = tg; p < 2 * MT * H_ * (DR_ / 2); p += nThreads) {
        float* buf = (p < MT * H_ * (DR_ / 2)) ? qr : kr;
        int pp = p & (MT * H_ * (DR_ / 2) - 1);
        int i  = pp & 31;
        int h  = (pp >> 5) & (H_ - 1);
        int bt = pp >> 9;
        int t = bt & (T_ - 1);

        float fi = (float)i;
        float base_inv = exp2f(-(2.0f * fi / 64.0f) * LOG2_10000);
        float ramp = fminf(fmaxf((fi - 1.0f) / 31.0f, 0.0f), 1.0f);
        float inv = base_inv * (1.0f - ramp) + (base_inv * (1.0f / 32.0f)) * ramp;
        float fr = (float)t * inv;
        float c = cosf(fr) * YARN_F;
        float s = sinf(fr) * YARN_F;

        size_t base = (size_t)bt * (H_ * DR_) + h * DR_;
        float x1 = buf[base + i];
        float x2 = buf[base + i + 32];
        buf[base + i]      = x1 * c - x2 * s;
        buf[base + i + 32] = x2 * c + x1 * s;
    }
}

// ---------------------------------------------------------------------------
// Launch [4]: output projection.
// ---------------------------------------------------------------------------
__global__ __launch_bounds__(256, 2)
void wo_kernel(const float* __restrict__ ao, const float* __restrict__ w_o,
               float* __restrict__ out) {
    extern __shared__ float smem[];
    int bx = blockIdx.x, by = blockIdx.y;
    gemm_core_128(ao + (size_t)(by * BM) * D_, w_o + bx * 128,
                  out + (size_t)(by * BM) * D_ + bx * 128, D_, D_, smem);
}

// ---------------------------------------------------------------------------
// Sparse attention (one batch per launch; grid (64, 16)) — UNCHANGED from the
// measured R14 kernel (397us/launch, issue 54%, L1 75%).
// ---------------------------------------------------------------------------
#define KT 32
#define QT 32
#define KSLD 196
#define ATTN_Q_FL   (32 * 192)
#define ATTN_K_FL   (32 * KSLD)
#define ATTN_V_FL   (32 * 128)
#define ATTN_P_FL   (8 * 4 * 32)
#define ATTN_SMEM_BYTES ((ATTN_Q_FL + ATTN_K_FL + ATTN_V_FL + ATTN_P_FL + 512) * 4)

__global__ __launch_bounds__(256, 2)
void attn_kernel(const float* __restrict__ qc, const float* __restrict__ kc,
                 const float* __restrict__ vc, const float* __restrict__ qr,
                 const float* __restrict__ kr, float* __restrict__ ao,
                 int batch) {
    extern __shared__ float smem[];
    float* Qs = smem;                          // [32][192]
    float* Ks = Qs + ATTN_Q_FL;                // [32][196]
    float* Vs = Ks + ATTN_K_FL;                // [32][128]
    float* Ps = Vs + ATTN_V_FL;                // [8][4][32]
    int* keys_sm = (int*)(Ps + ATTN_P_FL);     // [512]

    const int tid  = threadIdx.x;
    const int lane = tid & 31;
    const int warp = tid >> 5;
    const int q0 = blockIdx.x * QT;
    const int h  = blockIdx.y;
    const int b  = batch;

    // --- enumerate candidate keys (disjoint: global | dilated | window) ---
    int lo   = max(0, q0 - WINDOW_HALF);
    int aEnd = min(lo, GLOBAL_);
    int nB   = (lo > GLOBAL_) ? (((lo - 1) >> 6) - 1) : 0;
    int hi   = q0 + QT - 1;
    int nW   = hi - lo + 1;
    int cnt  = aEnd + nB + nW;
    int cntPad = (cnt + KT - 1) & ~(KT - 1);
    for (int s = tid; s < cntPad; s += 256) {
        int k;
        if (s < aEnd)           k = s;
        else if (s < aEnd + nB) k = GLOBAL_ + 64 * (s - aEnd);
        else if (s < cnt)       k = lo + (s - aEnd - nB);
        else                    k = -1;
        keys_sm[s] = k;
    }

    const float* qc_base = qc + ((size_t)b * T_) * D_ + h * DH_;
    const float* qr_base = qr + ((size_t)b * T_) * (H_ * DR_) + h * DR_;
    const float* kc_base = kc + ((size_t)b * T_) * D_ + h * DH_;
    const float* kr_base = kr + ((size_t)b * T_) * (H_ * DR_) + h * DR_;
    const float* vc_base = vc + ((size_t)b * T_) * D_ + h * DH_;

    // per-thread staging coordinates (fixed across tiles)
    const int kR[6] = { tid / 48, (tid + 256) / 48, (tid + 512) / 48,
                        (tid + 768) / 48, (tid + 1024) / 48, (tid + 1280) / 48 };
    const int kJ[6] = { tid % 48, (tid + 256) % 48, (tid + 512) % 48,
                        (tid + 768) % 48, (tid + 1024) % 48, (tid + 1280) % 48 };
    const int vJ = tid & 31;

    auto gather_tile = [&](int s0, float4* kp, float4* vp) {
#pragma unroll
        for (int it = 0; it < 6; it++) {
            int kid = keys_sm[s0 + kR[it]];
            int krow = kid < 0 ? 0 : kid;
            int j = kJ[it];
            kp[it] = (j < 32)
                ? *(const float4*)(kc_base + (size_t)krow * D_ + 4 * j)
                : *(const float4*)(kr_base + (size_t)krow * (H_*DR_) + 4 * (j - 32));
        }
#pragma unroll
        for (int it = 0; it < 4; it++) {
            int r = (tid + it * 256) >> 5;
            int kid = keys_sm[s0 + r];
            int krow = kid < 0 ? 0 : kid;
            vp[it] = *(const float4*)(vc_base + (size_t)krow * D_ + 4 * vJ);
        }
    };
    auto store_tile = [&](const float4* kp, const float4* vp) {
#pragma unroll
        for (int it = 0; it < 6; it++)
            *(float4*)(Ks + kR[it] * KSLD + 4 * kJ[it]) = kp[it];
#pragma unroll
        for (int it = 0; it < 4; it++) {
            int r = (tid + it * 256) >> 5;
            *(float4*)(Vs + r * 128 + 4 * vJ) = vp[it];
        }
    };

    // --- stage pre-scaled Q tile: [0,128)=qc*SCALE ; [128,192)=qr*SCALE_ROPE
#pragma unroll
    for (int it = 0; it < 6; it++) {
        int r = kR[it], j = kJ[it];
        float4 v;
        float sc;
        if (j < 32) { v = *(const float4*)(qc_base + (size_t)(q0 + r) * D_ + 4 * j); sc = SCALE_CF; }
        else        { v = *(const float4*)(qr_base + (size_t)(q0 + r) * (H_*DR_) + 4 * (j - 32)); sc = SCALE_ROPE_CF; }
        v.x *= sc; v.y *= sc; v.z *= sc; v.w *= sc;
        *(float4*)(Qs + r * 192 + 4 * j) = v;
    }

    // keys_sm written cooperatively above; fence before first cross-thread read.
    __syncthreads();

    // prologue: stage tile 0
    {
        float4 kp[6], vp[4];
        gather_tile(0, kp, vp);
        store_tile(kp, vp);
    }

    float m[4], l[4];
    float4 acc[4];
#pragma unroll
    for (int i = 0; i < 4; i++) {
        m[i] = -INFINITY; l[i] = 0.f;
        acc[i] = make_float4(0.f, 0.f, 0.f, 0.f);
    }

    __syncthreads();

    const float4* Q4[4];
#pragma unroll
    for (int i = 0; i < 4; i++) Q4[i] = (const float4*)(Qs + (warp * 4 + i) * 192);

    for (int s0 = 0; s0 < cntPad; s0 += KT) {
        const bool has = (s0 + KT) < cntPad;
        float4 kp[6], vp[4];
        if (has) gather_tile(s0 + KT, kp, vp);   // LDGs in flight during compute

        // ---- scores: lane's key vs warp's 4 queries (no shuffles) ----
        int myk = keys_sm[s0 + lane];
        const float4* Krow = (const float4*)(Ks + lane * KSLD);
        float sc0 = 0.f, sc1 = 0.f, sc2 = 0.f, sc3 = 0.f;
#pragma unroll 8
        for (int dv = 0; dv < 48; dv++) {
            float4 k4 = Krow[dv];
            float4 a;
            a = Q4[0][dv]; sc0 += k4.x*a.x + k4.y*a.y + k4.z*a.z + k4.w*a.w;
            a = Q4[1][dv]; sc1 += k4.x*a.x + k4.y*a.y + k4.z*a.z + k4.w*a.w;
            a = Q4[2][dv]; sc2 += k4.x*a.x + k4.y*a.y + k4.z*a.z + k4.w*a.w;
            a = Q4[3][dv]; sc3 += k4.x*a.x + k4.y*a.y + k4.z*a.z + k4.w*a.w;
        }
        float sc[4] = {sc0, sc1, sc2, sc3};

        // ---- mask + online softmax per query; write p to smem ----
#pragma unroll
        for (int i = 0; i < 4; i++) {
            int q = q0 + warp * 4 + i;
            bool valid = (myk >= 0) & (myk <= q) &&
                         ((q - myk) <= WINDOW_HALF || myk < GLOBAL_ ||
                          (myk & (STRIDE_ - 1)) == 0);
            float si = valid ? sc[i] : -INFINITY;
            float mx = si;
#pragma unroll
            for (int off = 16; off; off >>= 1)
                mx = fmaxf(mx, __shfl_xor_sync(0xffffffffu, mx, off));
            float mnew = fmaxf(m[i], mx);
            float corr = __expf(m[i] - mnew);          // exp(-inf)=0 on first tile
            float p = __expf(si - mnew);
            float ps = p;
#pragma unroll
            for (int off = 16; off; off >>= 1)
                ps += __shfl_xor_sync(0xffffffffu, ps, off);
            l[i] = l[i] * corr + ps;
            m[i] = mnew;
            acc[i].x *= corr; acc[i].y *= corr; acc[i].z *= corr; acc[i].w *= corr;
            Ps[warp * 128 + i * 32 + lane] = p;
        }
        __syncwarp();

        // ---- accumulate V: lane owns dims [4*lane, 4*lane+4) ----
        const float4* V4 = (const float4*)Vs;
        const float* Pw = Ps + warp * 128;
#pragma unroll 4
        for (int u = 0; u < 32; u++) {
            float4 v4 = V4[u * 32 + lane];
            float p0 = Pw[u];
            float p1 = Pw[32 + u];
            float p2 = Pw[64 + u];
            float p3 = Pw[96 + u];
            acc[0].x += p0 * v4.x; acc[0].y += p0 * v4.y; acc[0].z += p0 * v4.z; acc[0].w += p0 * v4.w;
            acc[1].x += p1 * v4.x; acc[1].y += p1 * v4.y; acc[1].z += p1 * v4.z; acc[1].w += p1 * v4.w;
            acc[2].x += p2 * v4.x; acc[2].y += p2 * v4.y; acc[2].z += p2 * v4.z; acc[2].w += p2 * v4.w;
            acc[3].x += p3 * v4.x; acc[3].y += p3 * v4.y; acc[3].z += p3 * v4.z; acc[3].w += p3 * v4.w;
        }

        __syncthreads();              // all reads of Ks/Vs complete
        if (has) store_tile(kp, vp);  // STS next tile
        __syncthreads();              // staged data visible
    }

    // ---- epilogue: lane writes its 4 dims of each query ----
    float* ao_base = ao + ((size_t)b * T_) * D_ + h * DH_;
#pragma unroll
    for (int i = 0; i < 4; i++) {
        int q = q0 + warp * 4 + i;
        float inv_l = 1.0f / l[i];
        float4 o = make_float4(acc[i].x * inv_l, acc[i].y * inv_l,
                               acc[i].z * inv_l, acc[i].w * inv_l);
        *(float4*)(ao_base + (size_t)q * D_ + 4 * lane) = o;
    }
}

// ---------------------------------------------------------------------------
// Launch: [0] xproj  [1] ukuv+rope  [2] attn b0  [3] attn b1  [4] w_o
// ---------------------------------------------------------------------------
extern "C" void kernel_launch(void* const* d_in, const int* in_sizes, int n_in,
                              void* d_out, int out_size) {
    (void)in_sizes; (void)n_in; (void)out_size;
    const float* x     = (const float*)d_in[0];
    const float* w_q   = (const float*)d_in[1];
    const float* w_dkv = (const float*)d_in[2];
    const float* w_uk  = (const float*)d_in[3];
    const float* w_uv  = (const float*)d_in[4];
    const float* w_qp  = (const float*)d_in[5];
    const float* w_kp  = (const float*)d_in[6];
    const float* w_o   = (const float*)d_in[7];
    float* out = (float*)d_out;

    float *qc, *ckv, *kc, *vc, *qr, *kr, *ao;
    cudaGetSymbolAddress((void**)&qc,  g_qc);
    cudaGetSymbolAddress((void**)&ckv, g_ckv);
    cudaGetSymbolAddress((void**)&kc,  g_kc);
    cudaGetSymbolAddress((void**)&vc,  g_vc);
    cudaGetSymbolAddress((void**)&qr,  g_qr);
    cudaGetSymbolAddress((void**)&kr,  g_kr);
    cudaGetSymbolAddress((void**)&ao,  g_ao);

    cudaFuncSetAttribute(xproj_kernel, cudaFuncAttributeMaxDynamicSharedMemorySize,
                         GEMM_SMEM_BYTES);
    cudaFuncSetAttribute(ukuv_rope_kernel, cudaFuncAttributeMaxDynamicSharedMemorySize,
                         GEMM_SMEM_BYTES);
    cudaFuncSetAttribute(wo_kernel, cudaFuncAttributeMaxDynamicSharedMemorySize,
                         GEMM_SMEM_BYTES);
    cudaFuncSetAttribute(attn_kernel, cudaFuncAttributeMaxDynamicSharedMemorySize,
                         ATTN_SMEM_BYTES);

    // [0] all x-projections (qc, ckv, qr, kr)
    xproj_kernel<<<dim3(36, 32), 256, GEMM_SMEM_BYTES>>>(
        x, w_q, w_dkv, w_qp, w_kp, qc, ckv, qr, kr);

    // [1] uk/uv GEMMs + rope(qr, kr)
    ukuv_rope_kernel<<<dim3(16, 32, 3), 256, GEMM_SMEM_BYTES>>>(
        ckv, w_uk, w_uv, kc, vc, qr, kr);

    // [2],[3] sparse attention per batch
    attn_kernel<<<dim3(T_ / QT, H_), 256, ATTN_SMEM_BYTES>>>(qc, kc, vc, qr, kr, ao, 0);
    attn_kernel<<<dim3(T_ / QT, H_), 256, ATTN_SMEM_BYTES>>>(qc, kc, vc, qr, kr, ao, 1);

    // [4] output projection
    wo_kernel<<<dim3(16, 32), 256, GEMM_SMEM_BYTES>>>(ao, w_o, out);
}